// round 9
// baseline (speedup 1.0000x reference)
#include <cuda_runtime.h>
#include <cstdint>

// D3PM q_sample — bit-exact vs JAX threefry, partitionable mode (modern default):
//   split:  key_i = (o0, o1) of threefry2x32((0,42), (0, i))     [foldlike]
//   bits32: bits[i] = o0 ^ o1 of threefry2x32(key, (0, flat_idx)),
//           flat_idx row-major over (B, L, N)  [iota_2x32_shape, hi=0].
//
// OUTPUT IS FLOAT32 (this round's fix): all prior rounds failed with rel_err
// EXACTLY 1.0 — the signature of int32 writes read as float32 denormals (~0),
// giving ||0-ref||/||ref|| = 1. Token ids (<=516) are exact in float32.
//
// Input binding is permutation-proof: by SIZE on the host (two equal large =
// structure/sequence candidates), by CONTENT on the device (structure has
// values > 32; t's int bit patterns < 2^28, alpha's float32 patterns >= 2^28).
//
// Pruning theorem (exact, incl. a=0 edge): probs = a*onehot(x0)+(1-a)*onehot(M),
// logits = log(probs+1e-10), gumbel from clamped-[tiny,1) uniforms:
//   any "other" channel score <= log(1e-10) + g_max = -7.086
//   the higher-prob of {x0, M} >= log(0.5)   + g_min = -5.163
// so the global argmax is ALWAYS x0 or MASK -> 2 RNG draws per row.
// Ties -> lower class index (argmax takes first max).
//
// Output (float32): [0,R) noised_structure, [R,2R) noised_sequence, [2R,2R+B) t.

#define TINYF 1.17549435e-38f
#define EPSF  1e-10f

__device__ int g_sA;   // 1 if large-array A is `structure` (else B is)
__device__ int g_tC;   // 1 if small-array C is `t` (else D is)

__host__ __device__ __forceinline__ unsigned rotl32(unsigned x, int r) {
#ifdef __CUDA_ARCH__
    return __funnelshift_l(x, x, r);
#else
    return (x << r) | (x >> (32 - r));
#endif
}

// Standard threefry2x32, 20 rounds (matches jax/_src/prng.py lowering).
__host__ __device__ __forceinline__ void threefry2x32(
    unsigned k0, unsigned k1, unsigned m0, unsigned m1,
    unsigned& o0, unsigned& o1)
{
    const unsigned ks2 = 0x1BD11BDAu ^ k0 ^ k1;
    unsigned x0 = m0 + k0;
    unsigned x1 = m1 + k1;
#define TF_R(r) { x0 += x1; x1 = rotl32(x1, (r)) ^ x0; }
    TF_R(13) TF_R(15) TF_R(26) TF_R(6)
    x0 += k1;  x1 += ks2 + 1u;
    TF_R(17) TF_R(29) TF_R(16) TF_R(24)
    x0 += ks2; x1 += k0 + 2u;
    TF_R(13) TF_R(15) TF_R(26) TF_R(6)
    x0 += k0;  x1 += k1 + 3u;
    TF_R(17) TF_R(29) TF_R(16) TF_R(24)
    x0 += k1;  x1 += ks2 + 4u;
    TF_R(13) TF_R(15) TF_R(26) TF_R(6)
    x0 += ks2; x1 += k0 + 5u;
#undef TF_R
    o0 = x0; o1 = x1;
}

// Partitionable 32-bit stream at flat index i: o0 ^ o1 of F(key, (0, i)).
__device__ __forceinline__ unsigned jax_bits32(unsigned ka, unsigned kb, unsigned i) {
    unsigned o0, o1;
    threefry2x32(ka, kb, 0u, i, o0, o1);
    return o0 ^ o1;
}

// JAX gumbel: u = bitcast((bits>>9)|0x3f800000)-1; f = max(tiny, u*(1-tiny)+tiny)
// ((1-tiny) rounds to 1.0f in fp32); g = -log(-log(f)). libdevice logf = XLA log.
__device__ __forceinline__ float gumbel_from_bits(unsigned bits) {
    float u = __uint_as_float(0x3f800000u | (bits >> 9)) - 1.0f;
    float f = fmaxf(TINYF, u + TINYF);
    return -logf(-logf(f));
}

__device__ __forceinline__ float sample_row(
    int row, int x0, float a,
    unsigned ka, unsigned kb, int N, int MASK)
{
    if (x0 == MASK) return (float)x0;   // combined channel always wins
    unsigned b1 = jax_bits32(ka, kb, (unsigned)row * (unsigned)N + (unsigned)x0);
    unsigned b2 = jax_bits32(ka, kb, (unsigned)row * (unsigned)N + (unsigned)MASK);
    float vx = gumbel_from_bits(b1) + logf(a + EPSF);
    float vm = gumbel_from_bits(b2) + logf((1.0f - a) + EPSF);
    if (vx > vm) return (float)x0;
    if (vm > vx) return (float)MASK;
    return (float)((x0 < MASK) ? x0 : MASK);   // argmax first-max tie-break
}

// Content-based disambiguation:
//  - structure ~ U[0,516): max of 256 elems > 32 w.p. 1 - (33/516)^256;
//    sequence ~ U[0,33): always <= 32.
//  - t: ints in [1,500] (bit patterns < 2^28); alpha: float32 in ~(0.002,1),
//    alpha[0] ~ 0.998 -> bits ~0x3F7B.... >= 2^28.
__global__ void detect_kernel(const int* __restrict__ A, const int* __restrict__ B,
                              const unsigned* __restrict__ C)
{
    if (blockIdx.x == 0 && threadIdx.x == 0) {
        int maxA = 0, maxB = 0;
        for (int i = 0; i < 256; i++) {
            maxA = max(maxA, A[i]);
            maxB = max(maxB, B[i]);
        }
        g_sA = (maxA > maxB) ? 1 : 0;
        g_tC = (C[0] < 0x10000000u) ? 1 : 0;
    }
}

__global__ __launch_bounds__(256)
void d3pm_fused_kernel(const int* __restrict__ pA, const int* __restrict__ pB,
                       const void* __restrict__ pC, const void* __restrict__ pD,
                       float* __restrict__ out,
                       unsigned ksa, unsigned ksb,
                       unsigned kqa, unsigned kqb,
                       int rows, int sC, int sD)
{
    const int sA = g_sA, tC = g_tC;
    const int*   structure = sA ? pA : pB;
    const int*   sequence  = sA ? pB : pA;
    const int*   t         = tC ? (const int*)pC   : (const int*)pD;
    const float* alpha     = tC ? (const float*)pD : (const float*)pC;
    const int    Bv        = tC ? sC : sD;
    const int    L         = rows / Bv;

    int j = blockIdx.x * blockDim.x + threadIdx.x;
    if (j >= 2 * rows + Bv) return;

    if (j < rows) {
        // structure: N=516, MASK=3
        float a = alpha[t[j / L]];
        out[j] = sample_row(j, structure[j], a, ksa, ksb, 516, 3);
    } else if (j < 2 * rows) {
        // sequence: N=33, MASK=32
        int r = j - rows;
        float a = alpha[t[r / L]];
        out[j] = sample_row(r, sequence[r], a, kqa, kqb, 33, 32);
    } else {
        out[j] = (float)t[j - 2 * rows];
    }
}

extern "C" void kernel_launch(void* const* d_in, const int* in_sizes, int n_in,
                              void* d_out, int out_size)
{
    // Bind inputs by SIZE: two largest (equal) = structure/sequence candidates;
    // remaining two = t/alpha candidates (disambiguated on-device by content).
    int idx[4] = {0, 1, 2, 3};
    for (int i = 0; i < 3; i++)
        for (int k = i + 1; k < 4; k++)
            if (in_sizes[idx[k]] > in_sizes[idx[i]]) {
                int tmp = idx[i]; idx[i] = idx[k]; idx[k] = tmp;
            }
    const int iA = idx[0], iB = idx[1], iC = idx[2], iD = idx[3];

    const int*  pA = (const int*)d_in[iA];
    const int*  pB = (const int*)d_in[iB];
    const void* pC = d_in[iC];
    const void* pD = d_in[iD];
    const int rows = in_sizes[iA];          // B*L
    const int sC = in_sizes[iC], sD = in_sizes[iD];

    // key = jax.random.key(42) -> (0, 42)
    // partitionable (foldlike) split: key_i = (o0, o1) of F((0,42), (0, i))
    unsigned ksa, ksb, kqa, kqb;
    threefry2x32(0u, 42u, 0u, 0u, ksa, ksb);   // ks (structure)
    threefry2x32(0u, 42u, 0u, 1u, kqa, kqb);   // kq (sequence)

    detect_kernel<<<1, 32>>>(pA, pB, (const unsigned*)pC);

    const int total_max = 2 * rows + ((sC > sD) ? sC : sD);
    const int threads   = 256;
    const int blocks    = (total_max + threads - 1) / threads;

    d3pm_fused_kernel<<<blocks, threads>>>(
        pA, pB, pC, pD, (float*)d_out,
        ksa, ksb, kqa, kqb, rows, sC, sD);
}